// round 14
// baseline (speedup 1.0000x reference)
#include <cuda_runtime.h>
#include <cuda_bf16.h>
#include <cstdint>

#define C    85
#define SEQ  8192
#define NB   32
#define KCHK 4
#define KLEN 2048
#define ISD  0.10846522890932808f  // 1/sqrt(85)

// ---------------- device scratch ----------------
__device__ float g_hh[NB][KCHK][96 * 96];
__device__ float g_lh[NB][KCHK][96 * 96];
__device__ float g_spart[NB][KCHK][96];
__device__ float g_G[NB][96 * 96];
__device__ float g_s[NB][96];
__device__ __nv_bfloat16 g_Mhi[NB][96 * 96];
__device__ __nv_bfloat16 g_Mlo[NB][96 * 96];
__device__ float g_c[NB][C];
__device__ __nv_bfloat16 g_xhi[NB][C][SEQ];
__device__ __nv_bfloat16 g_xlo[NB][C][SEQ];

// ---------------- helpers ----------------
__device__ __forceinline__ uint32_t smem_u32(const void* p) {
    uint32_t a;
    asm("{ .reg .u64 t; cvta.to.shared.u64 t, %1; cvt.u32.u64 %0, t; }" : "=r"(a) : "l"(p));
    return a;
}
__device__ __forceinline__ void ldsm4(uint32_t& r0, uint32_t& r1, uint32_t& r2, uint32_t& r3,
                                      uint32_t addr) {
    asm volatile("ldmatrix.sync.aligned.m8n8.x4.shared.b16 {%0,%1,%2,%3}, [%4];"
                 : "=r"(r0), "=r"(r1), "=r"(r2), "=r"(r3) : "r"(addr));
}
__device__ __forceinline__ void ldsm4t(uint32_t& r0, uint32_t& r1, uint32_t& r2, uint32_t& r3,
                                       uint32_t addr) {
    asm volatile("ldmatrix.sync.aligned.m8n8.x4.trans.shared.b16 {%0,%1,%2,%3}, [%4];"
                 : "=r"(r0), "=r"(r1), "=r"(r2), "=r"(r3) : "r"(addr));
}
__device__ __forceinline__ void mma_bf16(float* d, const uint32_t* a, uint32_t b0, uint32_t b1) {
    asm volatile(
        "mma.sync.aligned.m16n8k16.row.col.f32.bf16.bf16.f32 "
        "{%0,%1,%2,%3},{%4,%5,%6,%7},{%8,%9},{%0,%1,%2,%3};"
        : "+f"(d[0]), "+f"(d[1]), "+f"(d[2]), "+f"(d[3])
        : "r"(a[0]), "r"(a[1]), "r"(a[2]), "r"(a[3]), "r"(b0), "r"(b1));
}
__device__ __forceinline__ void cp16(uint32_t daddr, const void* src) {
    asm volatile("cp.async.cg.shared.global [%0], [%1], 16;" :: "r"(daddr), "l"(src));
}

// ============ kernel 1: HMMA Gram partials + bf16 X split store ============
__global__ __launch_bounds__(256, 1) void k_gram(const float* __restrict__ x) {
    __shared__ __align__(128) uint8_t s_hi[96 * 128];
    __shared__ __align__(128) uint8_t s_lo[96 * 128];
    __shared__ float s_red[1536];
    const int b = blockIdx.y, kc = blockIdx.x;
    const int t = threadIdx.x, lane = t & 31, wid = t >> 5;
    const int q = t & 15, rst = t >> 4;
    const float* xb = x + (size_t)b * C * SEQ + (size_t)kc * KLEN;

    const uint32_t a_hi = smem_u32(s_hi), a_lo = smem_u32(s_lo);
    const int wr = wid >> 1, wc = wid & 1;
    const uint32_t a_A = (wr < 2) ? a_hi : a_lo;
    const int m0 = (wr & 1) * 48, n0 = wc * 48;

    float acc[3][6][4];
#pragma unroll
    for (int mt = 0; mt < 3; mt++)
#pragma unroll
        for (int nt = 0; nt < 6; nt++)
#pragma unroll
            for (int e = 0; e < 4; e++) acc[mt][nt][e] = 0.f;

    float4 v[6];
    float srow[6] = {0.f, 0.f, 0.f, 0.f, 0.f, 0.f};
#pragma unroll
    for (int i = 0; i < 6; i++) {
        const int r = rst + 16 * i;
        if (r < C) v[i] = *(const float4*)(xb + (size_t)r * SEQ + q * 4);
    }

    for (int s = 0; s < 32; ++s) {
        __syncthreads();
#pragma unroll
        for (int i = 0; i < 6; i++) {
            const int r = rst + 16 * i;
            if (r < C) {
                const float4 w = v[i];
                __nv_bfloat162 h01 = __floats2bfloat162_rn(w.x, w.y);
                __nv_bfloat162 h23 = __floats2bfloat162_rn(w.z, w.w);
                float2 f01 = __bfloat1622float2(h01);
                float2 f23 = __bfloat1622float2(h23);
                __nv_bfloat162 l01 = __floats2bfloat162_rn(w.x - f01.x, w.y - f01.y);
                __nv_bfloat162 l23 = __floats2bfloat162_rn(w.z - f23.x, w.w - f23.y);
                const uint32_t cb = (uint32_t)(q * 8) ^ (uint32_t)((r & 7) << 4);
                const uint2 hv = make_uint2(*(uint32_t*)&h01, *(uint32_t*)&h23);
                const uint2 lv = make_uint2(*(uint32_t*)&l01, *(uint32_t*)&l23);
                *(uint2*)(s_hi + r * 128 + cb) = hv;
                *(uint2*)(s_lo + r * 128 + cb) = lv;
                const size_t gl = (size_t)kc * KLEN + s * 64 + q * 4;
                *(uint2*)&g_xhi[b][r][gl] = hv;
                *(uint2*)&g_xlo[b][r][gl] = lv;
                srow[i] += (w.x + w.y) + (w.z + w.w);
            }
        }
        __syncthreads();
        if (s < 31) {
#pragma unroll
            for (int i = 0; i < 6; i++) {
                const int r = rst + 16 * i;
                if (r < C) v[i] = *(const float4*)(xb + (size_t)r * SEQ + (s + 1) * 64 + q * 4);
            }
        }
#pragma unroll
        for (int k = 0; k < 4; ++k) {
            uint32_t a[3][4], bb[3][4];
            const uint32_t cbA = 32 * k + ((lane & 16) ? 16 : 0);
#pragma unroll
            for (int mt = 0; mt < 3; mt++) {
                const int row = m0 + mt * 16 + (lane & 15);
                const uint32_t cb = cbA ^ ((row & 7) << 4);
                ldsm4(a[mt][0], a[mt][1], a[mt][2], a[mt][3], a_A + row * 128 + cb);
            }
            const uint32_t cbB = 32 * k + ((lane & 8) ? 16 : 0);
#pragma unroll
            for (int np = 0; np < 3; np++) {
                const int row = n0 + np * 16 + (lane & 7) + ((lane & 16) ? 8 : 0);
                const uint32_t cb = cbB ^ ((row & 7) << 4);
                ldsm4(bb[np][0], bb[np][1], bb[np][2], bb[np][3], a_hi + row * 128 + cb);
            }
#pragma unroll
            for (int mt = 0; mt < 3; mt++)
#pragma unroll
                for (int nt = 0; nt < 6; nt++) {
                    const int np = nt >> 1;
                    mma_bf16(acc[mt][nt], a[mt],
                             (nt & 1) ? bb[np][2] : bb[np][0],
                             (nt & 1) ? bb[np][3] : bb[np][1]);
                }
        }
    }

    float* base = (wr < 2) ? g_hh[b][kc] : g_lh[b][kc];
    const int rb = (wr & 1) * 48;
#pragma unroll
    for (int mt = 0; mt < 3; mt++) {
        const int row = rb + mt * 16 + (lane >> 2);
#pragma unroll
        for (int nt = 0; nt < 6; nt++) {
            const int col = n0 + nt * 8 + (lane & 3) * 2;
            *(float2*)&base[row * 96 + col] = make_float2(acc[mt][nt][0], acc[mt][nt][1]);
            *(float2*)&base[(row + 8) * 96 + col] = make_float2(acc[mt][nt][2], acc[mt][nt][3]);
        }
    }
#pragma unroll
    for (int i = 0; i < 6; i++) s_red[(rst + 16 * i) * 16 + q] = srow[i];
    __syncthreads();
    if (t < 96) {
        float a = 0.f;
#pragma unroll
        for (int qq = 0; qq < 16; qq++) a += s_red[t * 16 + qq];
        g_spart[b][kc][t] = a;
    }
}

// ============ kernel 2a: reduce partials -> G block, s.  grid (4, NB) ============
__global__ void k_red() {
    __shared__ float lhT[24 * 97];
    const int b = blockIdx.y, rcb = blockIdx.x, t = threadIdx.x;
    const int r0 = rcb * 24;
    for (int i = t; i < 24 * 96; i += 256) {
        const int rl = i % 24, c2 = i / 24;
        float a = 0.f;
#pragma unroll
        for (int k = 0; k < KCHK; k++) a += g_lh[b][k][c2 * 96 + r0 + rl];
        lhT[rl * 97 + c2] = a;
    }
    if (rcb == 0 && t < 96) {
        float a = 0.f;
#pragma unroll
        for (int k = 0; k < KCHK; k++) a += g_spart[b][k][t];
        g_s[b][t] = a;
    }
    __syncthreads();
    for (int i = t; i < 24 * 96; i += 256) {
        const int rl = i / 96, c2 = i % 96;
        const int r = r0 + rl;
        float a = 0.f;
#pragma unroll
        for (int k = 0; k < KCHK; k++)
            a += g_hh[b][k][r * 96 + c2] + g_lh[b][k][r * 96 + c2];
        g_G[b][r * 96 + c2] = a + lhT[rl * 97 + c2];
    }
}

// ============ kernel 2b: attention middle, 1 row per warp, grid (12, NB) ============
__global__ __launch_bounds__(256) void k_attn(const float* __restrict__ Wq,
                                              const float* __restrict__ Wk,
                                              const float* __restrict__ Wv,
                                              const float* __restrict__ bq,
                                              const float* __restrict__ bk,
                                              const float* __restrict__ bv) {
    extern __shared__ float asm_[];
    float* Gs  = asm_;
    float* Wks = asm_ + 7310;
    float* Wvs = asm_ + 14705;
    float* Hb  = asm_ + 22100;
    float* sWq = asm_ + 22804;
    float* ss  = asm_ + 23508;
    float* bks = asm_ + 23604;
    float* bvs = asm_ + 23700;
    const int b = blockIdx.y, rc = blockIdx.x, t = threadIdx.x;

    for (int i = t; i < 7225; i += 256) {
        const int r = i / 85, c2 = i % 85;
        Gs[r * 86 + c2] = g_G[b][r * 96 + c2];
        Wks[r * 87 + c2] = Wk[i];
        Wvs[r * 87 + c2] = Wv[i];
    }
    for (int i = t; i < 680; i += 256) {
        const int r = i / 85, e = i % 85;
        const int c = rc * 8 + r;
        sWq[r * 88 + e] = (c < C) ? Wq[c * C + e] : 0.f;
    }
    if (t < 96) ss[t] = g_s[b][t];
    if (t < 85) { bks[t] = bk[t]; bvs[t] = bv[t]; }
    __syncthreads();

    const int warp = t >> 5, lane = t & 31;
    const int c = rc * 8 + warp;
    const int d0 = lane, d1 = lane + 32, d2 = lane + 64;
    float* Hrow = &Hb[warp * 88];

    if (c >= C) {
        const __nv_bfloat16 z = __float2bfloat16(0.f);
        for (int f = lane; f < 96; f += 32) {
            g_Mhi[b][c * 96 + f] = z;
            g_Mlo[b][c * 96 + f] = z;
        }
        return;
    }

    float v0 = 0.f, v1 = 0.f, v2 = 0.f;
    for (int e = 0; e < C; e++) {
        const float se = ss[e];
        v0 += se * Wks[d0 * 87 + e];
        v1 += se * Wks[d1 * 87 + e];
        if (d2 < C) v2 += se * Wks[d2 * 87 + e];
    }

    float h0 = 0.f, h1 = 0.f, h2 = 0.f, uc = 0.f;
    const float* wqr = &sWq[warp * 88];
    for (int e = 0; e < C; e++) {
        const float wq = wqr[e];
        uc += wq * ss[e];
        h0 += wq * Gs[e * 86 + d0];
        h1 += wq * Gs[e * 86 + d1];
        if (d2 < C) h2 += wq * Gs[e * 86 + d2];
    }
    Hrow[d0] = h0; Hrow[d1] = h1;
    if (d2 < C) Hrow[d2] = h2;
    __syncwarp();

    float s0 = 0.f, s1 = 0.f, s2 = 0.f;
    for (int e = 0; e < C; e++) {
        const float h = Hrow[e];
        s0 += h * Wks[d0 * 87 + e];
        s1 += h * Wks[d1 * 87 + e];
        if (d2 < C) s2 += h * Wks[d2 * 87 + e];
    }
    const float bqc = __ldg(&bq[c]);
    s0 = (s0 + uc * bks[d0] + bqc * (v0 + (float)SEQ * bks[d0])) * ISD;
    s1 = (s1 + uc * bks[d1] + bqc * (v1 + (float)SEQ * bks[d1])) * ISD;
    s2 = (d2 < C) ? (s2 + uc * bks[d2] + bqc * (v2 + (float)SEQ * bks[d2])) * ISD : -1e30f;

    float m = fmaxf(s0, fmaxf(s1, s2));
#pragma unroll
    for (int o = 16; o > 0; o >>= 1) m = fmaxf(m, __shfl_xor_sync(0xffffffffu, m, o));
    float e0 = __expf(s0 - m), e1 = __expf(s1 - m), e2 = (d2 < C) ? __expf(s2 - m) : 0.f;
    float sum = e0 + e1 + e2;
#pragma unroll
    for (int o = 16; o > 0; o >>= 1) sum += __shfl_xor_sync(0xffffffffu, sum, o);
    const float inv = 1.f / sum;
    e0 *= inv; e1 *= inv; e2 *= inv;
    __syncwarp();
    Hrow[d0] = e0; Hrow[d1] = e1;
    if (d2 < C) Hrow[d2] = e2;
    __syncwarp();

    float m0 = 0.f, m1 = 0.f, m2 = 0.f;
    for (int a = 0; a < C; a++) {
        const float p = Hrow[a];
        m0 += p * Wvs[a * 87 + d0];
        m1 += p * Wvs[a * 87 + d1];
        if (d2 < C) m2 += p * Wvs[a * 87 + d2];
    }
    {
        const __nv_bfloat16 h0b = __float2bfloat16(m0);
        g_Mhi[b][c * 96 + d0] = h0b;
        g_Mlo[b][c * 96 + d0] = __float2bfloat16(m0 - __bfloat162float(h0b));
        const __nv_bfloat16 h1b = __float2bfloat16(m1);
        g_Mhi[b][c * 96 + d1] = h1b;
        g_Mlo[b][c * 96 + d1] = __float2bfloat16(m1 - __bfloat162float(h1b));
        if (d2 < C) {
            const __nv_bfloat16 h2b = __float2bfloat16(m2);
            g_Mhi[b][c * 96 + d2] = h2b;
            g_Mlo[b][c * 96 + d2] = __float2bfloat16(m2 - __bfloat162float(h2b));
        } else {
            const __nv_bfloat16 zz = __float2bfloat16(0.f);
            g_Mhi[b][c * 96 + d2] = zz;
            g_Mlo[b][c * 96 + d2] = zz;
        }
    }
    float cv = e0 * bvs[d0] + e1 * bvs[d1] + ((d2 < C) ? e2 * bvs[d2] : 0.f);
#pragma unroll
    for (int o = 16; o > 0; o >>= 1) cv += __shfl_xor_sync(0xffffffffu, cv, o);
    if (lane == 0) g_c[b][c] = cv;
}

// ============ kernel 3: out = M X + c 1^T, cp.async double-buffered ============
// grid (32 tile-pairs of 256 L, NB), 384 thr, warp grid 3(M)x4(N), warp tile 32x16
// smem: Mhi 24K @0 | Mlo 24K @24576 | X buf0 hi/lo 12K+12K @49152 | buf1 @73728
__global__ __launch_bounds__(384, 2) void k_out(float* __restrict__ out) {
    extern __shared__ __align__(128) uint8_t dsm[];
    const int b = blockIdx.y, tp = blockIdx.x;
    const int t = threadIdx.x, lane = t & 31, wid = t >> 5;
    const uint32_t uM0 = smem_u32(dsm);
    const uint32_t uXbase = uM0 + 49152;
    const size_t Lcta = (size_t)tp * 256;

    // zero pad rows 85..95 of all 4 X half-buffers (never touched by cp.async)
    if (t < 352) {
        const int hb = t / 88, rem = t % 88;
        const int r = 85 + rem / 8, c16 = rem % 8;
        const uint32_t off = 49152 + hb * 12288 + r * 128 + ((c16 * 16) ^ ((r & 7) << 4));
        *(uint4*)(dsm + off) = make_uint4(0u, 0u, 0u, 0u);
    }

    // issue cp.async for units 0,1
#pragma unroll
    for (int u = 0; u < 2; ++u) {
        const size_t Lb = Lcta + u * 64;
        const uint32_t xb = uXbase + u * 24576;
#pragma unroll
        for (int j = 0; j < 2; j++) {
            const int ci = t + 384 * j;
            const int r = ci >> 3, c16 = ci & 7;
            if (r < C) {
                const uint32_t doff = xb + r * 128 + ((c16 * 16) ^ ((r & 7) << 4));
                cp16(doff, &g_xhi[b][r][Lb + c16 * 8]);
                cp16(doff + 12288, &g_xlo[b][r][Lb + c16 * 8]);
            }
        }
        asm volatile("cp.async.commit_group;");
    }

    // stage M (bf16-split, swizzled, 256B rows)
    for (int ci = t; ci < 1152; ci += 384) {
        const int r = ci / 12;
        const uint32_t cb = (uint32_t)((ci % 12) * 16);
        const uint32_t sw = cb ^ ((r & 7) << 4);
        *(uint4*)(dsm + r * 256 + sw) = *(const uint4*)((const uint8_t*)g_Mhi[b] + ci * 16);
        *(uint4*)(dsm + 24576 + r * 256 + sw) =
            *(const uint4*)((const uint8_t*)g_Mlo[b] + ci * 16);
    }

    const int wr = wid >> 2, wc = wid & 3;
    const int m0 = wr * 32;

#pragma unroll
    for (int u = 0; u < 4; ++u) {
        if (u < 3) asm volatile("cp.async.wait_group 1;" ::: "memory");
        else       asm volatile("cp.async.wait_group 0;" ::: "memory");
        __syncthreads();
        const uint32_t uXh = uXbase + (u & 1) * 24576;
        const uint32_t uXl = uXh + 12288;

        float acc[2][2][4];
#pragma unroll
        for (int mt = 0; mt < 2; mt++)
#pragma unroll
            for (int nt = 0; nt < 2; nt++)
#pragma unroll
                for (int e = 0; e < 4; e++) acc[mt][nt][e] = 0.f;

#pragma unroll
        for (int k = 0; k < 6; ++k) {
            uint32_t ahi[2][4], alo[2][4], bh[4], bl[4];
            const uint32_t cbA = 32 * k + ((lane & 16) ? 16 : 0);
#pragma unroll
            for (int mt = 0; mt < 2; mt++) {
                const int row = m0 + mt * 16 + (lane & 15);
                const uint32_t sw = cbA ^ ((row & 7) << 4);
                ldsm4(ahi[mt][0], ahi[mt][1], ahi[mt][2], ahi[mt][3], uM0 + row * 256 + sw);
                ldsm4(alo[mt][0], alo[mt][1], alo[mt][2], alo[mt][3],
                      uM0 + 24576 + row * 256 + sw);
            }
            const int rowB = 16 * k + (lane & 7) + ((lane & 8) ? 8 : 0);
            const uint32_t cbn =
                (uint32_t)(wc * 32 + ((lane & 16) ? 16 : 0)) ^ ((rowB & 7) << 4);
            ldsm4t(bh[0], bh[1], bh[2], bh[3], uXh + rowB * 128 + cbn);
            ldsm4t(bl[0], bl[1], bl[2], bl[3], uXl + rowB * 128 + cbn);
#pragma unroll
            for (int mt = 0; mt < 2; mt++)
#pragma unroll
                for (int nt = 0; nt < 2; nt++) {
                    const uint32_t bh0 = nt ? bh[2] : bh[0];
                    const uint32_t bh1 = nt ? bh[3] : bh[1];
                    const uint32_t bl0 = nt ? bl[2] : bl[0];
                    const uint32_t bl1 = nt ? bl[3] : bl[1];
                    mma_bf16(acc[mt][nt], ahi[mt], bh0, bh1);
                    mma_bf16(acc[mt][nt], ahi[mt], bl0, bl1);
                    mma_bf16(acc[mt][nt], alo[mt], bh0, bh1);
                }
        }

        // epilogue for this unit
#pragma unroll
        for (int mt = 0; mt < 2; mt++) {
            const int row = m0 + mt * 16 + (lane >> 2);
            const float c0 = (row < C) ? g_c[b][row] : 0.f;
            const float c1 = (row + 8 < C) ? g_c[b][row + 8] : 0.f;
#pragma unroll
            for (int nt = 0; nt < 2; nt++) {
                const size_t col = Lcta + u * 64 + wc * 16 + nt * 8 + (lane & 3) * 2;
                if (row < C)
                    *(float2*)(out + (size_t)b * C * SEQ + (size_t)row * SEQ + col) =
                        make_float2(acc[mt][nt][0] + c0, acc[mt][nt][1] + c0);
                if (row + 8 < C)
                    *(float2*)(out + (size_t)b * C * SEQ + (size_t)(row + 8) * SEQ + col) =
                        make_float2(acc[mt][nt][2] + c1, acc[mt][nt][3] + c1);
            }
        }
        __syncthreads();

        if (u < 2) {  // issue unit u+2 into buffer u&1
            const size_t Lb = Lcta + (u + 2) * 64;
            const uint32_t xb = uXbase + (u & 1) * 24576;
#pragma unroll
            for (int j = 0; j < 2; j++) {
                const int ci = t + 384 * j;
                const int r = ci >> 3, c16 = ci & 7;
                if (r < C) {
                    const uint32_t doff = xb + r * 128 + ((c16 * 16) ^ ((r & 7) << 4));
                    cp16(doff, &g_xhi[b][r][Lb + c16 * 8]);
                    cp16(doff + 12288, &g_xlo[b][r][Lb + c16 * 8]);
                }
            }
            asm volatile("cp.async.commit_group;");
        }
    }
}

extern "C" void kernel_launch(void* const* d_in, const int* in_sizes, int n_in,
                              void* d_out, int out_size) {
    const float* x  = (const float*)d_in[0];
    const float* Wq = (const float*)d_in[1];
    const float* bq = (const float*)d_in[2];
    const float* Wk = (const float*)d_in[3];
    const float* bk = (const float*)d_in[4];
    const float* Wv = (const float*)d_in[5];
    const float* bv = (const float*)d_in[6];
    float* out = (float*)d_out;

    static bool attr_done = false;
    if (!attr_done) {
        cudaFuncSetAttribute(k_attn, cudaFuncAttributeMaxDynamicSharedMemorySize, 95184);
        cudaFuncSetAttribute(k_out, cudaFuncAttributeMaxDynamicSharedMemorySize, 98304);
        attr_done = true;
    }

    k_gram<<<dim3(KCHK, NB), 256>>>(x);
    k_red<<<dim3(4, NB), 256>>>();
    k_attn<<<dim3(12, NB), 256, 95184>>>(Wq, Wk, Wv, bq, bk, bv);
    k_out<<<dim3(32, NB), 384, 98304>>>(out);
}

// round 17
// speedup vs baseline: 1.1550x; 1.1550x over previous
#include <cuda_runtime.h>
#include <cuda_bf16.h>
#include <cstdint>

#define C    85
#define SEQ  8192
#define NB   32
#define KCHK 4
#define KLEN 2048
#define ISD  0.10846522890932808f  // 1/sqrt(85)

// ---------------- device scratch ----------------
__device__ float g_hh[NB][KCHK][96 * 96];
__device__ float g_lh[NB][KCHK][96 * 96];
__device__ float g_spart[NB][KCHK][96];
__device__ float g_G[NB][96 * 96];
__device__ float g_s[NB][96];
__device__ __nv_bfloat16 g_Mhi[NB][96 * 96];
__device__ __nv_bfloat16 g_Mlo[NB][96 * 96];
__device__ float g_c[NB][C];

// ---------------- helpers ----------------
__device__ __forceinline__ uint32_t smem_u32(const void* p) {
    uint32_t a;
    asm("{ .reg .u64 t; cvta.to.shared.u64 t, %1; cvt.u32.u64 %0, t; }" : "=r"(a) : "l"(p));
    return a;
}
__device__ __forceinline__ void ldsm4(uint32_t& r0, uint32_t& r1, uint32_t& r2, uint32_t& r3,
                                      uint32_t addr) {
    asm volatile("ldmatrix.sync.aligned.m8n8.x4.shared.b16 {%0,%1,%2,%3}, [%4];"
                 : "=r"(r0), "=r"(r1), "=r"(r2), "=r"(r3) : "r"(addr));
}
__device__ __forceinline__ void ldsm4t(uint32_t& r0, uint32_t& r1, uint32_t& r2, uint32_t& r3,
                                       uint32_t addr) {
    asm volatile("ldmatrix.sync.aligned.m8n8.x4.trans.shared.b16 {%0,%1,%2,%3}, [%4];"
                 : "=r"(r0), "=r"(r1), "=r"(r2), "=r"(r3) : "r"(addr));
}
__device__ __forceinline__ void mma_bf16(float* d, const uint32_t* a, uint32_t b0, uint32_t b1) {
    asm volatile(
        "mma.sync.aligned.m16n8k16.row.col.f32.bf16.bf16.f32 "
        "{%0,%1,%2,%3},{%4,%5,%6,%7},{%8,%9},{%0,%1,%2,%3};"
        : "+f"(d[0]), "+f"(d[1]), "+f"(d[2]), "+f"(d[3])
        : "r"(a[0]), "r"(a[1]), "r"(a[2]), "r"(a[3]), "r"(b0), "r"(b1));
}

// ============ kernel 1: HMMA Gram partials (R6/R12 version, verbatim) ============
__global__ __launch_bounds__(256, 1) void k_gram(const float* __restrict__ x) {
    __shared__ __align__(128) uint8_t s_hi[96 * 128];
    __shared__ __align__(128) uint8_t s_lo[96 * 128];
    __shared__ float s_red[1536];
    const int b = blockIdx.y, kc = blockIdx.x;
    const int t = threadIdx.x, lane = t & 31, wid = t >> 5;
    const int q = t & 15, rst = t >> 4;
    const float* xb = x + (size_t)b * C * SEQ + (size_t)kc * KLEN;

    const uint32_t a_hi = smem_u32(s_hi), a_lo = smem_u32(s_lo);
    const int wr = wid >> 1, wc = wid & 1;
    const uint32_t a_A = (wr < 2) ? a_hi : a_lo;
    const int m0 = (wr & 1) * 48, n0 = wc * 48;

    float acc[3][6][4];
#pragma unroll
    for (int mt = 0; mt < 3; mt++)
#pragma unroll
        for (int nt = 0; nt < 6; nt++)
#pragma unroll
            for (int e = 0; e < 4; e++) acc[mt][nt][e] = 0.f;

    float4 v[6];
    float srow[6] = {0.f, 0.f, 0.f, 0.f, 0.f, 0.f};
#pragma unroll
    for (int i = 0; i < 6; i++) {
        const int r = rst + 16 * i;
        if (r < C) v[i] = *(const float4*)(xb + (size_t)r * SEQ + q * 4);
    }

    for (int s = 0; s < 32; ++s) {
        __syncthreads();
#pragma unroll
        for (int i = 0; i < 6; i++) {
            const int r = rst + 16 * i;
            if (r < C) {
                const float4 w = v[i];
                __nv_bfloat162 h01 = __floats2bfloat162_rn(w.x, w.y);
                __nv_bfloat162 h23 = __floats2bfloat162_rn(w.z, w.w);
                float2 f01 = __bfloat1622float2(h01);
                float2 f23 = __bfloat1622float2(h23);
                __nv_bfloat162 l01 = __floats2bfloat162_rn(w.x - f01.x, w.y - f01.y);
                __nv_bfloat162 l23 = __floats2bfloat162_rn(w.z - f23.x, w.w - f23.y);
                const uint32_t cb = (uint32_t)(q * 8) ^ (uint32_t)((r & 7) << 4);
                *(uint2*)(s_hi + r * 128 + cb) =
                    make_uint2(*(uint32_t*)&h01, *(uint32_t*)&h23);
                *(uint2*)(s_lo + r * 128 + cb) =
                    make_uint2(*(uint32_t*)&l01, *(uint32_t*)&l23);
                srow[i] += (w.x + w.y) + (w.z + w.w);
            }
        }
        __syncthreads();
        if (s < 31) {
#pragma unroll
            for (int i = 0; i < 6; i++) {
                const int r = rst + 16 * i;
                if (r < C) v[i] = *(const float4*)(xb + (size_t)r * SEQ + (s + 1) * 64 + q * 4);
            }
        }
#pragma unroll
        for (int k = 0; k < 4; ++k) {
            uint32_t a[3][4], bb[3][4];
            const uint32_t cbA = 32 * k + ((lane & 16) ? 16 : 0);
#pragma unroll
            for (int mt = 0; mt < 3; mt++) {
                const int row = m0 + mt * 16 + (lane & 15);
                const uint32_t cb = cbA ^ ((row & 7) << 4);
                ldsm4(a[mt][0], a[mt][1], a[mt][2], a[mt][3], a_A + row * 128 + cb);
            }
            const uint32_t cbB = 32 * k + ((lane & 8) ? 16 : 0);
#pragma unroll
            for (int np = 0; np < 3; np++) {
                const int row = n0 + np * 16 + (lane & 7) + ((lane & 16) ? 8 : 0);
                const uint32_t cb = cbB ^ ((row & 7) << 4);
                ldsm4(bb[np][0], bb[np][1], bb[np][2], bb[np][3], a_hi + row * 128 + cb);
            }
#pragma unroll
            for (int mt = 0; mt < 3; mt++)
#pragma unroll
                for (int nt = 0; nt < 6; nt++) {
                    const int np = nt >> 1;
                    mma_bf16(acc[mt][nt], a[mt],
                             (nt & 1) ? bb[np][2] : bb[np][0],
                             (nt & 1) ? bb[np][3] : bb[np][1]);
                }
        }
    }

    float* base = (wr < 2) ? g_hh[b][kc] : g_lh[b][kc];
    const int rb = (wr & 1) * 48;
#pragma unroll
    for (int mt = 0; mt < 3; mt++) {
        const int row = rb + mt * 16 + (lane >> 2);
#pragma unroll
        for (int nt = 0; nt < 6; nt++) {
            const int col = n0 + nt * 8 + (lane & 3) * 2;
            *(float2*)&base[row * 96 + col] = make_float2(acc[mt][nt][0], acc[mt][nt][1]);
            *(float2*)&base[(row + 8) * 96 + col] = make_float2(acc[mt][nt][2], acc[mt][nt][3]);
        }
    }
#pragma unroll
    for (int i = 0; i < 6; i++) s_red[(rst + 16 * i) * 16 + q] = srow[i];
    __syncthreads();
    if (t < 96) {
        float a = 0.f;
#pragma unroll
        for (int qq = 0; qq < 16; qq++) a += s_red[t * 16 + qq];
        g_spart[b][kc][t] = a;
    }
}

// ============ kernel 2a: reduce partials -> G block, s.  grid (4, NB) ============
__global__ void k_red() {
    __shared__ float lhT[24 * 97];
    const int b = blockIdx.y, rcb = blockIdx.x, t = threadIdx.x;
    const int r0 = rcb * 24;
    for (int i = t; i < 24 * 96; i += 256) {
        const int rl = i % 24, c2 = i / 24;
        float a = 0.f;
#pragma unroll
        for (int k = 0; k < KCHK; k++) a += g_lh[b][k][c2 * 96 + r0 + rl];
        lhT[rl * 97 + c2] = a;
    }
    if (rcb == 0 && t < 96) {
        float a = 0.f;
#pragma unroll
        for (int k = 0; k < KCHK; k++) a += g_spart[b][k][t];
        g_s[b][t] = a;
    }
    __syncthreads();
    for (int i = t; i < 24 * 96; i += 256) {
        const int rl = i / 96, c2 = i % 96;
        const int r = r0 + rl;
        float a = 0.f;
#pragma unroll
        for (int k = 0; k < KCHK; k++)
            a += g_hh[b][k][r * 96 + c2] + g_lh[b][k][r * 96 + c2];
        g_G[b][r * 96 + c2] = a + lhT[rl * 97 + c2];
    }
}

// ============ kernel 2b: attention middle, 1 row per warp, grid (12, NB) ============
// Slim smem: only Wk staged (row-access pattern is uncoalesced in gmem).
// G and Wv read directly from gmem — both coalesced (lanes span consecutive d/f) and L2-hot.
__global__ __launch_bounds__(256) void k_attn(const float* __restrict__ Wq,
                                              const float* __restrict__ Wk,
                                              const float* __restrict__ Wv,
                                              const float* __restrict__ bq,
                                              const float* __restrict__ bk,
                                              const float* __restrict__ bv) {
    extern __shared__ float asm_[];
    float* Wks = asm_;                 // 85x87 = 7395
    float* Hb  = asm_ + 7395;          // 8x88  = 704
    float* sWq = asm_ + 8099;          // 8x88  = 704
    float* ss  = asm_ + 8803;          // 96
    float* bks = asm_ + 8899;          // 96
    float* bvs = asm_ + 8995;          // 96  (total 9091 floats = 36364 B)
    const int b = blockIdx.y, rc = blockIdx.x, t = threadIdx.x;

    for (int i = t; i < 7225; i += 256)
        Wks[(i / 85) * 87 + (i % 85)] = Wk[i];
    for (int i = t; i < 680; i += 256) {
        const int r = i / 85, e = i % 85;
        const int c = rc * 8 + r;
        sWq[r * 88 + e] = (c < C) ? Wq[c * C + e] : 0.f;
    }
    if (t < 96) ss[t] = g_s[b][t];
    if (t < 85) { bks[t] = bk[t]; bvs[t] = bv[t]; }
    __syncthreads();

    const int warp = t >> 5, lane = t & 31;
    const int c = rc * 8 + warp;
    const int d0 = lane, d1 = lane + 32, d2 = lane + 64;
    float* Hrow = &Hb[warp * 88];

    if (c >= C) {
        const __nv_bfloat16 z = __float2bfloat16(0.f);
        for (int f = lane; f < 96; f += 32) {
            g_Mhi[b][c * 96 + f] = z;
            g_Mlo[b][c * 96 + f] = z;
        }
        return;
    }

    // v[d] = Wk[d,:] . s
    float v0 = 0.f, v1 = 0.f, v2 = 0.f;
    for (int e = 0; e < C; e++) {
        const float se = ss[e];
        v0 += se * Wks[d0 * 87 + e];
        v1 += se * Wks[d1 * 87 + e];
        if (d2 < C) v2 += se * Wks[d2 * 87 + e];
    }

    // stage 1: H[c,:] = Wq[c,:] G (G columns read direct from gmem, coalesced, L2-hot)
    float h0 = 0.f, h1 = 0.f, h2 = 0.f, uc = 0.f;
    const float* wqr = &sWq[warp * 88];
    const float* Gb = g_G[b];
#pragma unroll 5
    for (int e = 0; e < C; e++) {
        const float wq = wqr[e];
        uc += wq * ss[e];
        h0 += wq * __ldg(Gb + e * 96 + d0);
        h1 += wq * __ldg(Gb + e * 96 + d1);
        if (d2 < C) h2 += wq * __ldg(Gb + e * 96 + d2);
    }
    Hrow[d0] = h0; Hrow[d1] = h1;
    if (d2 < C) Hrow[d2] = h2;
    __syncwarp();

    // stage 2: S[c,d] = H[c,:] . Wk[d,:] + bias terms
    float s0 = 0.f, s1 = 0.f, s2 = 0.f;
    for (int e = 0; e < C; e++) {
        const float h = Hrow[e];
        s0 += h * Wks[d0 * 87 + e];
        s1 += h * Wks[d1 * 87 + e];
        if (d2 < C) s2 += h * Wks[d2 * 87 + e];
    }
    const float bqc = __ldg(&bq[c]);
    s0 = (s0 + uc * bks[d0] + bqc * (v0 + (float)SEQ * bks[d0])) * ISD;
    s1 = (s1 + uc * bks[d1] + bqc * (v1 + (float)SEQ * bks[d1])) * ISD;
    s2 = (d2 < C) ? (s2 + uc * bks[d2] + bqc * (v2 + (float)SEQ * bks[d2])) * ISD : -1e30f;

    // stage 3: softmax over d
    float m = fmaxf(s0, fmaxf(s1, s2));
#pragma unroll
    for (int o = 16; o > 0; o >>= 1) m = fmaxf(m, __shfl_xor_sync(0xffffffffu, m, o));
    float e0 = __expf(s0 - m), e1 = __expf(s1 - m), e2 = (d2 < C) ? __expf(s2 - m) : 0.f;
    float sum = e0 + e1 + e2;
#pragma unroll
    for (int o = 16; o > 0; o >>= 1) sum += __shfl_xor_sync(0xffffffffu, sum, o);
    const float inv = 1.f / sum;
    e0 *= inv; e1 *= inv; e2 *= inv;
    __syncwarp();
    Hrow[d0] = e0; Hrow[d1] = e1;
    if (d2 < C) Hrow[d2] = e2;
    __syncwarp();

    // stage 4: M[c,:] = P[c,:] Wv (Wv rows read direct from gmem, coalesced, L2-hot)
    float m0 = 0.f, m1 = 0.f, m2 = 0.f;
#pragma unroll 5
    for (int a = 0; a < C; a++) {
        const float p = Hrow[a];
        m0 += p * __ldg(Wv + a * C + d0);
        m1 += p * __ldg(Wv + a * C + d1);
        if (d2 < C) m2 += p * __ldg(Wv + a * C + d2);
    }
    {
        const __nv_bfloat16 h0b = __float2bfloat16(m0);
        g_Mhi[b][c * 96 + d0] = h0b;
        g_Mlo[b][c * 96 + d0] = __float2bfloat16(m0 - __bfloat162float(h0b));
        const __nv_bfloat16 h1b = __float2bfloat16(m1);
        g_Mhi[b][c * 96 + d1] = h1b;
        g_Mlo[b][c * 96 + d1] = __float2bfloat16(m1 - __bfloat162float(h1b));
        if (d2 < C) {
            const __nv_bfloat16 h2b = __float2bfloat16(m2);
            g_Mhi[b][c * 96 + d2] = h2b;
            g_Mlo[b][c * 96 + d2] = __float2bfloat16(m2 - __bfloat162float(h2b));
        } else {
            const __nv_bfloat16 zz = __float2bfloat16(0.f);
            g_Mhi[b][c * 96 + d2] = zz;
            g_Mlo[b][c * 96 + d2] = zz;
        }
    }
    float cv = e0 * bvs[d0] + e1 * bvs[d1] + ((d2 < C) ? e2 * bvs[d2] : 0.f);
#pragma unroll
    for (int o = 16; o > 0; o >>= 1) cv += __shfl_xor_sync(0xffffffffu, cv, o);
    if (lane == 0) g_c[b][c] = cv;
}

// ============ kernel 3: out = M X + c 1^T via HMMA, 384 thr (R12 version, verbatim) ============
__global__ __launch_bounds__(384, 2) void k_out(const float* __restrict__ x,
                                                float* __restrict__ out) {
    extern __shared__ __align__(128) uint8_t dsm[];
    uint8_t* sMhi = dsm;
    uint8_t* sMlo = dsm + 24576;
    uint8_t* sXhi = dsm + 49152;
    uint8_t* sXlo = dsm + 73728;
    const int b = blockIdx.y, tile = blockIdx.x;
    const int t = threadIdx.x, lane = t & 31, wid = t >> 5;
    const uint32_t uMhi = smem_u32(sMhi), uMlo = smem_u32(sMlo);
    const uint32_t uXhi = smem_u32(sXhi), uXlo = smem_u32(sXlo);

    for (int ci = t; ci < 1152; ci += 384) {
        const int r = ci / 12;
        const uint32_t cb = (uint32_t)((ci % 12) * 16);
        const uint32_t sw = cb ^ ((r & 7) << 4);
        *(uint4*)(sMhi + r * 256 + sw) = *(const uint4*)((const uint8_t*)g_Mhi[b] + ci * 16);
        *(uint4*)(sMlo + r * 256 + sw) = *(const uint4*)((const uint8_t*)g_Mlo[b] + ci * 16);
    }
    const float* xb = x + (size_t)b * C * SEQ + tile * 128;
#pragma unroll
    for (int i = 0; i < 8; i++) {
        const int idx = t + 384 * i;
        const int r = idx >> 5, c4 = idx & 31;
        const uint32_t cb = (uint32_t)(c4 * 8) ^ ((r & 7) << 4);
        uint2 hv = make_uint2(0u, 0u), lv = make_uint2(0u, 0u);
        if (r < C) {
            const float4 w = *(const float4*)(xb + (size_t)r * SEQ + c4 * 4);
            __nv_bfloat162 h01 = __floats2bfloat162_rn(w.x, w.y);
            __nv_bfloat162 h23 = __floats2bfloat162_rn(w.z, w.w);
            float2 f01 = __bfloat1622float2(h01);
            float2 f23 = __bfloat1622float2(h23);
            __nv_bfloat162 l01 = __floats2bfloat162_rn(w.x - f01.x, w.y - f01.y);
            __nv_bfloat162 l23 = __floats2bfloat162_rn(w.z - f23.x, w.w - f23.y);
            hv = make_uint2(*(uint32_t*)&h01, *(uint32_t*)&h23);
            lv = make_uint2(*(uint32_t*)&l01, *(uint32_t*)&l23);
        }
        *(uint2*)(sXhi + r * 256 + cb) = hv;
        *(uint2*)(sXlo + r * 256 + cb) = lv;
    }
    __syncthreads();

    const int wr = wid >> 2, wc = wid & 3;
    const int m0 = wr * 32, n0 = wc * 32;
    float acc[2][4][4];
#pragma unroll
    for (int mt = 0; mt < 2; mt++)
#pragma unroll
        for (int nt = 0; nt < 4; nt++)
#pragma unroll
            for (int e = 0; e < 4; e++) acc[mt][nt][e] = 0.f;

#pragma unroll
    for (int k = 0; k < 6; ++k) {
        uint32_t ahi[2][4], alo[2][4], bhi[2][4], blo[2][4];
        const uint32_t cbA = 32 * k + ((lane & 16) ? 16 : 0);
#pragma unroll
        for (int mt = 0; mt < 2; mt++) {
            const int row = m0 + mt * 16 + (lane & 15);
            const uint32_t sw = cbA ^ ((row & 7) << 4);
            ldsm4(ahi[mt][0], ahi[mt][1], ahi[mt][2], ahi[mt][3], uMhi + row * 256 + sw);
            ldsm4(alo[mt][0], alo[mt][1], alo[mt][2], alo[mt][3], uMlo + row * 256 + sw);
        }
        const int rowB = 16 * k + (lane & 7) + ((lane & 8) ? 8 : 0);
#pragma unroll
        for (int np = 0; np < 2; np++) {
            const uint32_t cbn = (uint32_t)(n0 * 2 + np * 32 + ((lane & 16) ? 16 : 0));
            const uint32_t sw = cbn ^ ((rowB & 7) << 4);
            ldsm4t(bhi[np][0], bhi[np][1], bhi[np][2], bhi[np][3], uXhi + rowB * 256 + sw);
            ldsm4t(blo[np][0], blo[np][1], blo[np][2], blo[np][3], uXlo + rowB * 256 + sw);
        }
#pragma unroll
        for (int mt = 0; mt < 2; mt++)
#pragma unroll
            for (int nt = 0; nt < 4; nt++) {
                const int np = nt >> 1;
                const uint32_t bh0 = (nt & 1) ? bhi[np][2] : bhi[np][0];
                const uint32_t bh1 = (nt & 1) ? bhi[np][3] : bhi[np][1];
                const uint32_t bl0 = (nt & 1) ? blo[np][2] : blo[np][0];
                const uint32_t bl1 = (nt & 1) ? blo[np][3] : blo[np][1];
                mma_bf16(acc[mt][nt], ahi[mt], bh0, bh1);
                mma_bf16(acc[mt][nt], ahi[mt], bl0, bl1);
                mma_bf16(acc[mt][nt], alo[mt], bh0, bh1);
            }
    }

#pragma unroll
    for (int mt = 0; mt < 2; mt++) {
        const int row = m0 + mt * 16 + (lane >> 2);
        const float c0 = (row < C) ? g_c[b][row] : 0.f;
        const float c1 = (row + 8 < C) ? g_c[b][row + 8] : 0.f;
#pragma unroll
        for (int nt = 0; nt < 4; nt++) {
            const int col = tile * 128 + n0 + nt * 8 + (lane & 3) * 2;
            if (row < C)
                *(float2*)(out + (size_t)b * C * SEQ + (size_t)row * SEQ + col) =
                    make_float2(acc[mt][nt][0] + c0, acc[mt][nt][1] + c0);
            if (row + 8 < C)
                *(float2*)(out + (size_t)b * C * SEQ + (size_t)(row + 8) * SEQ + col) =
                    make_float2(acc[mt][nt][2] + c1, acc[mt][nt][3] + c1);
        }
    }
}

extern "C" void kernel_launch(void* const* d_in, const int* in_sizes, int n_in,
                              void* d_out, int out_size) {
    const float* x  = (const float*)d_in[0];
    const float* Wq = (const float*)d_in[1];
    const float* bq = (const float*)d_in[2];
    const float* Wk = (const float*)d_in[3];
    const float* bk = (const float*)d_in[4];
    const float* Wv = (const float*)d_in[5];
    const float* bv = (const float*)d_in[6];
    float* out = (float*)d_out;

    static bool attr_done = false;
    if (!attr_done) {
        cudaFuncSetAttribute(k_attn, cudaFuncAttributeMaxDynamicSharedMemorySize, 36368);
        cudaFuncSetAttribute(k_out, cudaFuncAttributeMaxDynamicSharedMemorySize, 98304);
        attr_done = true;
    }

    k_gram<<<dim3(KCHK, NB), 256>>>(x);
    k_red<<<dim3(4, NB), 256>>>();
    k_attn<<<dim3(12, NB), 256, 36368>>>(Wq, Wk, Wv, bq, bk, bv);
    k_out<<<dim3(64, NB), 384, 98304>>>(x, out);
}